// round 2
// baseline (speedup 1.0000x reference)
#include <cuda_runtime.h>

#define N_NODES 10000
#define D_FEAT  128
#define BATCH   8192
#define K_NEIGH 25

__global__ void __launch_bounds__(256) mean_agg_kernel(
    const int*   __restrict__ nodes,      // [BATCH]           (int32)
    const int*   __restrict__ neigh_idx,  // [BATCH, K]        (int32)
    const float* __restrict__ feat,       // [N_NODES, D_FEAT]
    const float* __restrict__ adj,        // [N_NODES, N_NODES]
    const float* __restrict__ fsim,       // [N_NODES, N_NODES]
    float*       __restrict__ out)        // [BATCH, D_FEAT]
{
    const int warp = (blockIdx.x * blockDim.x + threadIdx.x) >> 5;
    const int lane = threadIdx.x & 31;
    if (warp >= BATCH) return;

    const int row = nodes[warp];

    // Lanes 0..24 each gather one neighbor weight.
    int   my_idx = 0;
    float my_w   = 0.0f;
    if (lane < K_NEIGH) {
        my_idx = neigh_idx[warp * K_NEIGH + lane];
        const long long base = (long long)row * N_NODES + my_idx;
        my_w = adj[base] + fsim[base];
    }

    // denom = sum of weights (lanes >= 25 hold 0)
    float denom = my_w;
    #pragma unroll
    for (int off = 16; off; off >>= 1)
        denom += __shfl_xor_sync(0xffffffffu, denom, off);

    // Accumulate weighted features: each lane owns 4 contiguous dims (float4).
    float4 acc = make_float4(0.f, 0.f, 0.f, 0.f);
    const float4* __restrict__ feat4 = (const float4*)feat;

    #pragma unroll
    for (int k = 0; k < K_NEIGH; k++) {
        const float wk = __shfl_sync(0xffffffffu, my_w, k);
        const int   ik = __shfl_sync(0xffffffffu, my_idx, k);
        const float4 f = feat4[ik * (D_FEAT / 4) + lane];
        acc.x += wk * f.x;
        acc.y += wk * f.y;
        acc.z += wk * f.z;
        acc.w += wk * f.w;
    }

    const float inv = 1.0f / denom;
    float4 o;
    o.x = acc.x * inv;
    o.y = acc.y * inv;
    o.z = acc.z * inv;
    o.w = acc.w * inv;
    ((float4*)out)[warp * (D_FEAT / 4) + lane] = o;
}

extern "C" void kernel_launch(void* const* d_in, const int* in_sizes, int n_in,
                              void* d_out, int out_size)
{
    const int*   nodes = (const int*)d_in[0];
    const int*   neigh = (const int*)d_in[1];
    const float* feat  = (const float*)d_in[2];
    const float* adj   = (const float*)d_in[3];
    const float* fsim  = (const float*)d_in[4];
    float*       out   = (float*)d_out;

    const int threads = 256;                                   // 8 warps/block
    const int blocks  = (BATCH * 32 + threads - 1) / threads;  // 1024 blocks
    mean_agg_kernel<<<blocks, threads>>>(nodes, neigh, feat, adj, fsim, out);
}